// round 17
// baseline (speedup 1.0000x reference)
#include <cuda_runtime.h>
#include <cuda_bf16.h>
#include <cstdint>

#define BB 8
#define SS 4096
#define HH 1024
#define KK 2048      // K = 0.5 * S
#define NBIN 4096    // uniform bins over score in (0,1)
#define MAXC 256     // candidate cap (E ~1-6 in practice)

__device__ float    g_scores[BB * SS];
__device__ int      g_hist[BB * NBIN];    // zeroed at load; re-zeroed by tail
__device__ int      g_ticket[BB];         // zeroed at load; reset by emit
__device__ uint32_t g_cutkey[BB];
__device__ int      g_cutidx[BB];

__device__ __forceinline__ uint32_t orderable(float f) {
    uint32_t u = __float_as_uint(f);
    return u ^ ((u >> 31) ? 0xFFFFFFFFu : 0x80000000u);
}
__device__ __forceinline__ int score_bin(float s) {
    int b = (int)(s * 4096.0f);
    return min(max(b, 0), NBIN - 1);
}

// ---------------------------------------------------------------------------
// Fused: GEMV (1 token/warp, 8 tokens/block, 512 blocks/row) + LEAN
// per-row threshold-find in the last block of each row (no emit here).
// ---------------------------------------------------------------------------
__global__ __launch_bounds__(256) void router_fused_kernel(
    const float* __restrict__ x, const float* __restrict__ w,
    float* __restrict__ scores, int* __restrict__ hist_g,
    int* __restrict__ ticket_g, uint32_t* __restrict__ cutkey_g,
    int* __restrict__ cutidx_g)
{
    __shared__ int      s_last;
    __shared__ int      s_wsum[8];
    __shared__ int      s_wexcl[8];
    __shared__ int      s_P, s_T, s_cnt;
    __shared__ uint32_t s_ckey[MAXC];
    __shared__ int      s_cidx[MAXC];
    __shared__ uint32_t s_ck;
    __shared__ int      s_ci;

    const int tid  = threadIdx.x;
    const int lane = tid & 31;
    const int wid  = tid >> 5;
    const int row  = blockIdx.x >> 9;               // 512 blocks per row

    // ---- GEMV: 8 tokens, one per warp ----
    {
        int gw = blockIdx.x * 8 + wid;              // token index
        const float4* xp = reinterpret_cast<const float4*>(x + (size_t)gw * HH);
        const float4* wp = reinterpret_cast<const float4*>(w);

        float acc = 0.0f;
#pragma unroll
        for (int i = 0; i < 8; i++) {               // 8 * 32 * 4 = 1024 = H
            int idx = lane + i * 32;
            float4 a = __ldcs(&xp[idx]);
            float4 b = __ldg(&wp[idx]);
            acc = fmaf(a.x, b.x, acc);
            acc = fmaf(a.y, b.y, acc);
            acc = fmaf(a.z, b.z, acc);
            acc = fmaf(a.w, b.w, acc);
        }
#pragma unroll
        for (int o = 16; o; o >>= 1)
            acc += __shfl_xor_sync(0xFFFFFFFFu, acc, o);

        if (lane == 0) {
            float s = 1.0f / (1.0f + expf(-acc));
            scores[gw] = s;
            atomicAdd(&hist_g[row * NBIN + score_bin(s)], 1);
        }
    }

    // ---- Last-block ticket ----
    __syncthreads();
    if (tid == 0) {
        __threadfence();
        s_last = (atomicAdd(&ticket_g[row], 1) == 511);
    }
    __syncthreads();
    if (!s_last) return;

    // =======================================================================
    // Lean tail (256 threads): scan 4096 bins -> bin P + quota T, rank the
    // few candidates in bin P -> (cut_key, cut_idx). Overlaps remaining GEMV
    // for rows 0..6; only row 7's ~1us tail is exposed.
    // =======================================================================
    int* hrow = hist_g + row * NBIN;

    // 16 bins per thread via 4 int4 loads; re-zero for next replay.
    int h[16];
    {
        const int4* hp = reinterpret_cast<const int4*>(hrow + tid * 16);
#pragma unroll
        for (int q = 0; q < 4; q++) {
            int4 hv = hp[q];
            h[q * 4 + 0] = hv.x; h[q * 4 + 1] = hv.y;
            h[q * 4 + 2] = hv.z; h[q * 4 + 3] = hv.w;
        }
        int4* hz = reinterpret_cast<int4*>(hrow + tid * 16);
#pragma unroll
        for (int q = 0; q < 4; q++) hz[q] = make_int4(0, 0, 0, 0);
    }
    int part = 0;
#pragma unroll
    for (int j = 0; j < 16; j++) part += h[j];

    if (tid == 0) s_cnt = 0;

    // Ascending inclusive scan of thread sums (8 warps).
    int inc = part;
#pragma unroll
    for (int o = 1; o < 32; o <<= 1) {
        int t = __shfl_up_sync(0xFFFFFFFFu, inc, o);
        if (lane >= o) inc += t;
    }
    if (lane == 31) s_wsum[wid] = inc;
    __syncthreads();
    if (tid == 0) {
        int r = 0;
#pragma unroll
        for (int wq = 0; wq < 8; wq++) { s_wexcl[wq] = r; r += s_wsum[wq]; }
    }
    __syncthreads();

    {
        const int incl_asc = s_wexcl[wid] + inc;    // through bin 16*tid+15
        const int above    = SS - incl_asc;         // keys in higher bins
        if (above < KK && above + part >= KK) {     // unique crossing thread
            int acc = above;
#pragma unroll
            for (int j = 15; j >= 0; j--) {
                if (acc + h[j] >= KK) {
                    s_P = tid * 16 + j;
                    s_T = KK - acc;
                    break;
                }
                acc += h[j];
            }
        }
    }
    __syncthreads();

    // Collect candidates in bin P (E tiny under uniform binning).
    const int P = s_P;
    const float4* rf4 = reinterpret_cast<const float4*>(scores + row * SS);
#pragma unroll
    for (int c = 0; c < 4; c++) {
        float4 lv = rf4[tid + c * 256];
        float vv[4] = {lv.x, lv.y, lv.z, lv.w};
#pragma unroll
        for (int i = 0; i < 4; i++) {
            if (score_bin(vv[i]) == P) {
                int pos = atomicAdd(&s_cnt, 1);
                if (pos < MAXC) {
                    s_ckey[pos] = orderable(vv[i]);
                    s_cidx[pos] = (tid + c * 256) * 4 + i;
                }
            }
        }
    }
    __syncthreads();

    // Exact cutoff: rank T-1 in (key desc, idx asc) — resolves ties exactly.
    const int E = min(s_cnt, MAXC);
    const int T = s_T;
    for (int c = tid; c < E; c += 256) {
        uint32_t ck = s_ckey[c];
        int      ci = s_cidx[c];
        int better = 0;
        for (int e = 0; e < E; e++) {
            uint32_t ek = s_ckey[e];
            better += (ek > ck) || (ek == ck && s_cidx[e] < ci);
        }
        if (better == T - 1) { s_ck = ck; s_ci = ci; }
    }
    __syncthreads();

    if (tid == 0) {
        cutkey_g[row] = s_ck;
        cutidx_g[row] = s_ci;
    }
}

// ---------------------------------------------------------------------------
// Wide emit: 32 blocks x 256 threads = 8192 threads, exactly one float4 of
// weights + one float4 of mask per thread (B*S = 32768 elements = 8192 f4).
// Accept iff (key,idx) >= cutoff in (key desc, idx asc). Resets tickets.
// ---------------------------------------------------------------------------
__global__ __launch_bounds__(256) void emit_kernel(
    const float* __restrict__ scores, const uint32_t* __restrict__ cutkey_g,
    const int* __restrict__ cutidx_g, int* __restrict__ ticket_g,
    float* __restrict__ out, int out_size)
{
    const int f4i = blockIdx.x * 256 + threadIdx.x;   // 0..8191  (exact)
    if (blockIdx.x == 0 && threadIdx.x < BB)
        ticket_g[threadIdx.x] = 0;                    // reset for next replay

    const int e = f4i * 4;                            // 0..32764
    const int b = e >> 12;                            // row (SS = 4096)

    const uint32_t ck = __ldg(&cutkey_g[b]);
    const int      ci = __ldg(&cutidx_g[b]);

    float4 lv = *reinterpret_cast<const float4*>(scores + e);
    float v[4] = {lv.x, lv.y, lv.z, lv.w};
    float wv4[4], mv4[4];
#pragma unroll
    for (int i = 0; i < 4; i++) {
        int s = (e & (SS - 1)) + i;
        uint32_t kk = orderable(v[i]);
        bool m = (kk > ck) || (kk == ck && s <= ci);
        wv4[i] = m ? v[i] : 0.0f;
        mv4[i] = m ? 1.0f : 0.0f;
    }
    *reinterpret_cast<float4*>(out + e) =
        make_float4(wv4[0], wv4[1], wv4[2], wv4[3]);
    if (out_size >= 2 * BB * SS)
        *reinterpret_cast<float4*>(out + BB * SS + e) =
            make_float4(mv4[0], mv4[1], mv4[2], mv4[3]);
}

extern "C" void kernel_launch(void* const* d_in, const int* in_sizes, int n_in,
                              void* d_out, int out_size)
{
    const float* hidden = (const float*)d_in[0];
    const float* w      = (const float*)d_in[1];
    float* out = (float*)d_out;

    float*    scores = nullptr;
    int*      hist   = nullptr;
    int*      ticket = nullptr;
    uint32_t* ckey   = nullptr;
    int*      cidx   = nullptr;
    cudaGetSymbolAddress((void**)&scores, g_scores);
    cudaGetSymbolAddress((void**)&hist,   g_hist);
    cudaGetSymbolAddress((void**)&ticket, g_ticket);
    cudaGetSymbolAddress((void**)&ckey,   g_cutkey);
    cudaGetSymbolAddress((void**)&cidx,   g_cutidx);

    router_fused_kernel<<<BB * 512, 256>>>(hidden, w, scores, hist,
                                           ticket, ckey, cidx);
    emit_kernel<<<(BB * SS) / 4 / 256, 256>>>(scores, ckey, cidx, ticket,
                                              out, out_size);
}